// round 15
// baseline (speedup 1.0000x reference)
#include <cuda_runtime.h>
#include <cstdint>

#define B_ 256
#define C_ 2048
#define N_ 288
#define K_ 6
#define NCTA_ 128
#define SLICES_ 16
#define BPW_ 8                 // batches per wave
#define WAVES_ 32
#define CSL_ 128               // C columns per slice
#define SLICE_BYTES (CSL_ * N_ * 4)     // 147456
#define HALF_BYTES (SLICE_BYTES / 2)    // 73728

typedef unsigned long long u64;

// scratch (no allocations allowed)
__device__ float g_part[(size_t)B_ * SLICES_ * 7 * N_];   // ~33 MB
__device__ volatile unsigned g_bar;

__device__ __forceinline__ u64 pack2(float lo, float hi) {
    u64 p;
    asm("mov.b64 %0, {%1, %2};" : "=l"(p) : "f"(lo), "f"(hi));
    return p;
}
__device__ __forceinline__ void unpack2(u64 p, float& lo, float& hi) {
    asm("mov.b64 {%0, %1}, %2;" : "=f"(lo), "=f"(hi) : "l"(p));
}
__device__ __forceinline__ float unpack_sum(u64 p) {
    float lo, hi;
    unpack2(p, lo, hi);
    return lo + hi;
}
__device__ __forceinline__ void fma2(u64& d, u64 a, u64 b) {
    asm("fma.rn.f32x2 %0, %1, %2, %3;" : "=l"(d) : "l"(a), "l"(b), "l"(d));
}
__device__ __forceinline__ uint32_t s2u(const void* p) {
    uint32_t a;
    asm("{ .reg .u64 t; cvta.to.shared.u64 t, %1; cvt.u32.u64 %0, t; }" : "=r"(a) : "l"(p));
    return a;
}
__device__ __forceinline__ void bulk_g2s(uint32_t dst, const void* src, uint32_t bytes, uint32_t mbar) {
    asm volatile("cp.async.bulk.shared::cta.global.mbarrier::complete_tx::bytes [%0], [%1], %2, [%3];"
                 :: "r"(dst), "l"(src), "r"(bytes), "r"(mbar) : "memory");
}
__device__ __forceinline__ void mbar_init(uint32_t a, uint32_t c) {
    asm volatile("mbarrier.init.shared.b64 [%0], %1;" :: "r"(a), "r"(c) : "memory");
}
__device__ __forceinline__ void mbar_expect(uint32_t a, uint32_t b) {
    asm volatile("mbarrier.arrive.expect_tx.shared.b64 _, [%0], %1;" :: "r"(a), "r"(b) : "memory");
}
__device__ __forceinline__ void mbar_wait(uint32_t a, uint32_t par) {
    uint32_t done;
    asm volatile("{\n\t.reg .pred p;\n\t"
                 "mbarrier.try_wait.parity.acquire.cta.shared::cta.b64 p, [%1], %2;\n\t"
                 "selp.b32 %0, 1, 0, p;\n\t}"
                 : "=r"(done) : "r"(a), "r"(par) : "memory");
    if (!done) {
        asm volatile("{\n\t.reg .pred P1;\n\t"
                     "WL_%=:\n\t"
                     "mbarrier.try_wait.parity.acquire.cta.shared::cta.b64 P1, [%0], %1, 0x989680;\n\t"
                     "@P1 bra.uni WD_%=;\n\t"
                     "bra.uni WL_%=;\n\t"
                     "WD_%=:\n\t}"
                     :: "r"(a), "r"(par) : "memory");
    }
}

__global__ void init_kernel() {
    if (threadIdx.x == 0) g_bar = 0;
}

// ---------------------------------------------------------------------------
// Fused single-x-read kernel. 128 CTAs x 288 thr, 1 CTA/SM (144KB dyn smem),
// all co-resident. 32 waves x 8 batches; CTA = (batch-in-wave bw, slice).
// Per wave: TMA-bulk x slice -> smem (2 halves, overlap dots on half 0);
// partial dots -> global; full-grid spin barrier; redundant argmin/counts;
// scatter-mean from smem (no 2nd DRAM read of x).
// ---------------------------------------------------------------------------
__global__ void __launch_bounds__(N_, 1) fused_kernel(const float* __restrict__ x,
                                                      const float* __restrict__ cl,
                                                      float* __restrict__ out) {
    extern __shared__ float sX[];                  // [CSL_][N_]
    __shared__ __align__(16) u64 sCl2T[CSL_ / 2][8];  // [c-pair][k] duplicated pairs
    __shared__ float sCn[K_], sInv[K_];
    __shared__ unsigned char sAssign[N_];
    __shared__ int sCnt[K_];
    __shared__ __align__(8) u64 mbarS[2];

    const int cta = blockIdx.x;
    const int bw = cta >> 4;                // 0..7
    const int slice = cta & 15;             // 0..15
    const int t = threadIdx.x;              // 0..287
    const int w = t >> 5;
    const int l = t & 31;

    const uint32_t sxa = s2u(sX);
    const uint32_t mb0 = s2u(&mbarS[0]);
    const uint32_t mb1 = s2u(&mbarS[1]);

    // cluster slice, duplicated pairs, [pair][k] for LDS.128 x3 per pair
    for (int i = t; i < K_ * (CSL_ / 2); i += N_) {
        int k = i / (CSL_ / 2), p = i % (CSL_ / 2);
        float a = cl[k * C_ + slice * CSL_ + 2 * p];
        float b2 = cl[k * C_ + slice * CSL_ + 2 * p + 1];
        sCl2T[p][k] = pack2(a, b2);
    }
    // full c_norm
    if (w < K_) {
        float s = 0.f;
        for (int c = l; c < C_; c += 32) {
            float v = __ldg(&cl[w * C_ + c]);
            s = fmaf(v, v, s);
        }
        #pragma unroll
        for (int o = 16; o; o >>= 1) s += __shfl_xor_sync(0xffffffffu, s, o);
        if (l == 0) sCn[w] = s;
    }
    if (t == 0) { mbar_init(mb0, 1); mbar_init(mb1, 1); }
    __syncthreads();

    for (int wv = 0; wv < WAVES_; wv++) {
        const int b = wv * BPW_ + bw;
        const int par = wv & 1;

        // ---------------- phase 1: bulk load + dots from smem ----------------
        const char* src = (const char*)x + ((size_t)b * C_ + (size_t)slice * CSL_) * N_ * 4;
        if (t == 0) {
            mbar_expect(mb0, HALF_BYTES);
            bulk_g2s(sxa, src, HALF_BYTES, mb0);
            mbar_expect(mb1, HALF_BYTES);
            bulk_g2s(sxa + HALF_BYTES, src + HALF_BYTES, HALF_BYTES, mb1);
        }

        u64 d2[K_];
        #pragma unroll
        for (int k = 0; k < K_; k++) d2[k] = 0ull;
        u64 xn2 = 0ull;

        #pragma unroll
        for (int half = 0; half < 2; half++) {
            mbar_wait(half ? mb1 : mb0, par);
            const int r0 = half * 64;
            #pragma unroll 1
            for (int c = r0; c < r0 + 64; c += 4) {
                #pragma unroll
                for (int pp = 0; pp < 2; pp++) {
                    const int cc = c + 2 * pp;
                    float va = sX[cc * N_ + t];
                    float vb = sX[(cc + 1) * N_ + t];
                    u64 vp = pack2(va, vb);
                    fma2(xn2, vp, vp);
                    const ulonglong2* cp2 = (const ulonglong2*)&sCl2T[cc >> 1][0];
                    ulonglong2 q0 = cp2[0];
                    ulonglong2 q1 = cp2[1];
                    ulonglong2 q2 = cp2[2];
                    fma2(d2[0], vp, q0.x);
                    fma2(d2[1], vp, q0.y);
                    fma2(d2[2], vp, q1.x);
                    fma2(d2[3], vp, q1.y);
                    fma2(d2[4], vp, q2.x);
                    fma2(d2[5], vp, q2.y);
                }
            }
        }

        {
            float* p = g_part + ((size_t)(b * SLICES_ + slice) * 7) * N_ + t;
            #pragma unroll
            for (int k = 0; k < K_; k++) p[k * N_] = unpack_sum(d2[k]);
            p[6 * N_] = unpack_sum(xn2);
        }

        // ---------------- global barrier (all 128 CTAs resident) -------------
        __threadfence();
        __syncthreads();
        if (t == 0) {
            atomicAdd((unsigned*)&g_bar, 1u);
            const unsigned tgt = (unsigned)NCTA_ * (unsigned)(wv + 1);
            while (g_bar < tgt) __nanosleep(64);
        }
        __syncthreads();
        __threadfence();

        // ---------------- phase 2: argmin + counts (redundant per CTA) -------
        if (t < K_) sCnt[t] = 0;
        __syncthreads();
        {
            float dot[K_];
            #pragma unroll
            for (int k = 0; k < K_; k++) dot[k] = 0.f;
            float xn = 0.f;
            #pragma unroll
            for (int s = 0; s < SLICES_; s++) {
                const float* p = g_part + ((size_t)(b * SLICES_ + s) * 7) * N_ + t;
                #pragma unroll
                for (int k = 0; k < K_; k++) dot[k] += __ldg(p + k * N_);
                xn += __ldg(p + 6 * N_);
            }
            int   a  = 0;
            float bd = (xn + sCn[0]) - 2.0f * dot[0];
            #pragma unroll
            for (int k = 1; k < K_; k++) {
                float e = (xn + sCn[k]) - 2.0f * dot[k];
                if (e < bd) { bd = e; a = k; }
            }
            sAssign[t] = (unsigned char)a;
            atomicAdd(&sCnt[a], 1);
        }
        __syncthreads();
        if (t < K_) {
            int cnt = sCnt[t];
            sInv[t] = (cnt > 0) ? (1.0f / (float)cnt) : 0.0f;
        }
        __syncthreads();

        // ---------------- phase 3: scatter-mean from smem --------------------
        {
            u64 m2[9][3];
            #pragma unroll
            for (int j = 0; j < 9; j++) {
                int a = (int)sAssign[j * 32 + l];
                #pragma unroll
                for (int p = 0; p < 3; p++)
                    m2[j][p] = pack2((a == 2 * p) ? 1.0f : 0.0f,
                                     (a == 2 * p + 1) ? 1.0f : 0.0f);
            }
            const bool hi = (l >= 16);
            const int  lk = l & 15;
            const int  myk = lk + (hi ? 3 : 0);
            const float invSel = (lk < 3) ? sInv[myk] : 0.0f;

            #pragma unroll 1
            for (int cr = w; cr < CSL_; cr += 9) {
                float v[9];
                #pragma unroll
                for (int j = 0; j < 9; j++) v[j] = sX[cr * N_ + j * 32 + l];

                u64 s2[3];
                #pragma unroll
                for (int p = 0; p < 3; p++) s2[p] = 0ull;
                #pragma unroll
                for (int j = 0; j < 9; j++) {
                    u64 vv = pack2(v[j], v[j]);
                    #pragma unroll
                    for (int p = 0; p < 3; p++) fma2(s2[p], m2[j][p], vv);
                }

                float s[K_];
                unpack2(s2[0], s[0], s[1]);
                unpack2(s2[1], s[2], s[3]);
                unpack2(s2[2], s[4], s[5]);

                float r0 = hi ? s[3] : s[0];
                float r1 = hi ? s[4] : s[1];
                float r2 = hi ? s[5] : s[2];
                float o0 = hi ? s[0] : s[3];
                float o1 = hi ? s[1] : s[4];
                float o2 = hi ? s[2] : s[5];
                r0 += __shfl_xor_sync(0xffffffffu, o0, 16);
                r1 += __shfl_xor_sync(0xffffffffu, o1, 16);
                r2 += __shfl_xor_sync(0xffffffffu, o2, 16);
                #pragma unroll
                for (int o = 8; o; o >>= 1) {
                    r0 += __shfl_xor_sync(0xffffffffu, r0, o);
                    r1 += __shfl_xor_sync(0xffffffffu, r1, o);
                    r2 += __shfl_xor_sync(0xffffffffu, r2, o);
                }

                float res = r0;
                res = (lk == 1) ? r1 : res;
                res = (lk == 2) ? r2 : res;
                if (lk < 3)
                    out[((size_t)b * C_ + (slice * CSL_ + cr)) * K_ + myk] = res * invSel;
            }
        }
        __syncthreads();   // sX / sAssign safe before next wave's bulk load
    }
}

extern "C" void kernel_launch(void* const* d_in, const int* in_sizes, int n_in,
                              void* d_out, int out_size) {
    const float* x  = (const float*)d_in[0];   // [256, 2048, 24, 12]
    const float* cl = (const float*)d_in[1];   // [6, 2048]
    float* out = (float*)d_out;                // [B, C, K]

    static int attr_set = 0;
    if (!attr_set) {
        cudaFuncSetAttribute(fused_kernel,
                             cudaFuncAttributeMaxDynamicSharedMemorySize, SLICE_BYTES);
        attr_set = 1;
    }

    init_kernel<<<1, 32>>>();
    fused_kernel<<<NCTA_, N_, SLICE_BYTES>>>(x, cl, out);
}

// round 17
// speedup vs baseline: 1.8562x; 1.8562x over previous
#include <cuda_runtime.h>

#define B_ 256
#define C_ 2048
#define N_ 288
#define K_ 6

typedef unsigned long long u64;

// scratch (no allocations allowed)
__device__ unsigned char g_assign[B_ * N_];
__device__ float g_inv[B_ * K_];
// partial dots: [512 half-blocks][7 (6 dots + xnorm)][288]
__device__ float g_part[(size_t)B_ * 2 * 7 * N_];

__device__ __forceinline__ u64 pack2(float lo, float hi) {
    u64 p;
    asm("mov.b64 %0, {%1, %2};" : "=l"(p) : "f"(lo), "f"(hi));
    return p;
}
__device__ __forceinline__ void unpack2(u64 p, float& lo, float& hi) {
    asm("mov.b64 {%0, %1}, %2;" : "=f"(lo), "=f"(hi) : "l"(p));
}
__device__ __forceinline__ float unpack_sum(u64 p) {
    float lo, hi;
    unpack2(p, lo, hi);
    return lo + hi;
}
__device__ __forceinline__ void fma2(u64& d, u64 a, u64 b) {
    asm("fma.rn.f32x2 %0, %1, %2, %3;" : "=l"(d) : "l"(a), "l"(b), "l"(d));
}

// ---------------------------------------------------------------------------
// Kernel A (R6, measured 113us @5.4TB/s): partial dots.
// grid = 2*B (CTA per (batch, C-half)), 288 threads (thread <-> n).
// ---------------------------------------------------------------------------
__global__ void __launch_bounds__(N_, 4) assign_part_kernel(const float* __restrict__ x,
                                                            const float* __restrict__ cl) {
    __shared__ float sCl[K_][1024];

    const int bx = blockIdx.x;
    const int b = bx >> 1;
    const int half = bx & 1;
    const int t = threadIdx.x;

    for (int i = t; i < K_ * 1024; i += N_) {
        int k = i >> 10, cc = i & 1023;
        sCl[k][cc] = cl[k * C_ + half * 1024 + cc];
    }
    __syncthreads();

    const float* xh = x + (size_t)b * ((size_t)C_ * N_) + (size_t)half * 1024 * N_ + t;

    u64 d2[K_];
    #pragma unroll
    for (int k = 0; k < K_; k++) d2[k] = 0ull;
    u64 xn2 = 0ull;

    float v[8], vn[8];
    #pragma unroll
    for (int u = 0; u < 8; u++) v[u] = xh[(size_t)u * N_];

    #pragma unroll 1
    for (int c = 0; c < 1024; c += 8) {
        if (c + 8 < 1024) {
            #pragma unroll
            for (int u = 0; u < 8; u++) vn[u] = xh[(size_t)(c + 8 + u) * N_];
        }
        u64 vp[4];
        #pragma unroll
        for (int u = 0; u < 4; u++) vp[u] = pack2(v[2 * u], v[2 * u + 1]);
        #pragma unroll
        for (int u = 0; u < 4; u++) fma2(xn2, vp[u], vp[u]);
        #pragma unroll
        for (int k = 0; k < K_; k++) {
            ulonglong2 q0 = *(const ulonglong2*)&sCl[k][c];
            ulonglong2 q1 = *(const ulonglong2*)&sCl[k][c + 4];
            fma2(d2[k], vp[0], q0.x);
            fma2(d2[k], vp[1], q0.y);
            fma2(d2[k], vp[2], q1.x);
            fma2(d2[k], vp[3], q1.y);
        }
        #pragma unroll
        for (int u = 0; u < 8; u++) v[u] = vn[u];
    }

    float* p = g_part + (size_t)bx * 7 * N_ + t;
    #pragma unroll
    for (int k = 0; k < K_; k++) p[k * N_] = unpack_sum(d2[k]);
    p[6 * N_] = unpack_sum(xn2);
}

// ---------------------------------------------------------------------------
// Kernel C: combine partials, argmin, counts. grid = B, 288 threads.
// ---------------------------------------------------------------------------
__global__ void __launch_bounds__(N_) argmin_kernel(const float* __restrict__ cl) {
    __shared__ float sCn[K_];
    __shared__ int   sCnt[K_];

    const int b = blockIdx.x;
    const int t = threadIdx.x;
    const int w = t >> 5;
    const int l = t & 31;

    if (t < K_) sCnt[t] = 0;

    if (w < K_) {
        float s = 0.f;
        for (int c = l; c < C_; c += 32) {
            float v = __ldg(&cl[w * C_ + c]);
            s = fmaf(v, v, s);
        }
        #pragma unroll
        for (int o = 16; o; o >>= 1) s += __shfl_xor_sync(0xffffffffu, s, o);
        if (l == 0) sCn[w] = s;
    }
    __syncthreads();

    const float* p0 = g_part + (size_t)(2 * b) * 7 * N_ + t;
    const float* p1 = g_part + (size_t)(2 * b + 1) * 7 * N_ + t;

    float xn = p0[6 * N_] + p1[6 * N_];
    int   a  = 0;
    float bd = (xn + sCn[0]) - 2.0f * (p0[0] + p1[0]);
    #pragma unroll
    for (int k = 1; k < K_; k++) {
        float e = (xn + sCn[k]) - 2.0f * (p0[k * N_] + p1[k * N_]);
        if (e < bd) { bd = e; a = k; }
    }
    g_assign[b * N_ + t] = (unsigned char)a;

    atomicAdd(&sCnt[a], 1);
    __syncthreads();
    if (t < K_) {
        int cnt = sCnt[t];
        g_inv[b * K_ + t] = (cnt > 0) ? (1.0f / (float)cnt) : 0.0f;
    }
}

// ---------------------------------------------------------------------------
// Kernel B: scatter-mean, ROW-PAIRED reduce. grid = 16*B CTAs of 128 threads.
// Warp <-> (b, 32 c-rows) processed as 16 row-pairs. Every lane accumulates
// partials for BOTH rows (A, B); a quarter-split reduce maps 8-lane groups to
// (row, k-triple): xor16 selects row, xor8 selects k-half, xor4/2/1 finish.
// 18 SHFL + 18 FADD per pair (vs 30+30), 18 loads in flight during reduce.
// ---------------------------------------------------------------------------
__global__ void __launch_bounds__(128, 5) sum_kernel(const float* __restrict__ x,
                                                     float* __restrict__ out) {
    const int b = blockIdx.x >> 4;
    const int q = blockIdx.x & 15;
    const int w = threadIdx.x >> 5;
    const int l = threadIdx.x & 31;

    // packed one-hot masks for this lane's 9 positions (fixed per batch)
    u64 m2[9][3];
    #pragma unroll
    for (int j = 0; j < 9; j++) {
        int a = (int)g_assign[b * N_ + j * 32 + l];
        #pragma unroll
        for (int p = 0; p < 3; p++)
            m2[j][p] = pack2((a == 2 * p) ? 1.0f : 0.0f,
                             (a == 2 * p + 1) ? 1.0f : 0.0f);
    }

    const int  grp   = l >> 3;              // 0..3
    const int  lk    = l & 7;
    const bool loHalf = (l < 16);           // keeps row A at xor16
    const bool loK    = ((l & 8) == 0);     // keeps k0..2 at xor8
    const int  myk   = (loK ? 0 : 3) + lk;  // valid when lk < 3
    const int  rowOff = (grp >= 2) ? 1 : 0; // groups 2,3 write row B
    const float invSel = (lk < 3) ? g_inv[b * K_ + myk] : 0.0f;

    const int c0 = q * 128 + w * 32;
    const float* rp = x + (size_t)b * ((size_t)C_ * N_) + (size_t)c0 * N_ + l;

    float v[9], v2[9];
    #pragma unroll
    for (int j = 0; j < 9; j++) v[j]  = rp[j * 32];
    #pragma unroll
    for (int j = 0; j < 9; j++) v2[j] = rp[N_ + j * 32];

    #pragma unroll 1
    for (int p = 0; p < 16; p++) {
        const int c = c0 + 2 * p;

        // accumulate both rows' partials (every lane computes both)
        u64 sA[3], sB[3];
        #pragma unroll
        for (int i = 0; i < 3; i++) { sA[i] = 0ull; sB[i] = 0ull; }
        #pragma unroll
        for (int j = 0; j < 9; j++) {
            u64 va = pack2(v[j], v[j]);
            #pragma unroll
            for (int i = 0; i < 3; i++) fma2(sA[i], m2[j][i], va);
        }
        #pragma unroll
        for (int j = 0; j < 9; j++) {
            u64 vb = pack2(v2[j], v2[j]);
            #pragma unroll
            for (int i = 0; i < 3; i++) fma2(sB[i], m2[j][i], vb);
        }

        // issue next pair's 18 loads before the reduce chain
        rp += 2 * N_;
        if (p + 1 < 16) {
            #pragma unroll
            for (int j = 0; j < 9; j++) v[j]  = rp[j * 32];
            #pragma unroll
            for (int j = 0; j < 9; j++) v2[j] = rp[N_ + j * 32];
        }

        float a0, a1, a2, a3, a4, a5, b0, b1, b2, b3, b4, b5;
        unpack2(sA[0], a0, a1); unpack2(sA[1], a2, a3); unpack2(sA[2], a4, a5);
        unpack2(sB[0], b0, b1); unpack2(sB[1], b2, b3); unpack2(sB[2], b4, b5);

        // xor16: keep own row's 6, send the other row's 6
        float k0, k1, k2, k3, k4, k5;
        {
            float s0 = loHalf ? b0 : a0, s1 = loHalf ? b1 : a1, s2_ = loHalf ? b2 : a2;
            float s3 = loHalf ? b3 : a3, s4 = loHalf ? b4 : a4, s5 = loHalf ? b5 : a5;
            k0 = (loHalf ? a0 : b0) + __shfl_xor_sync(0xffffffffu, s0, 16);
            k1 = (loHalf ? a1 : b1) + __shfl_xor_sync(0xffffffffu, s1, 16);
            k2 = (loHalf ? a2 : b2) + __shfl_xor_sync(0xffffffffu, s2_, 16);
            k3 = (loHalf ? a3 : b3) + __shfl_xor_sync(0xffffffffu, s3, 16);
            k4 = (loHalf ? a4 : b4) + __shfl_xor_sync(0xffffffffu, s4, 16);
            k5 = (loHalf ? a5 : b5) + __shfl_xor_sync(0xffffffffu, s5, 16);
        }
        // xor8: keep own k-triple, send the other
        float r0, r1, r2;
        {
            float s0 = loK ? k3 : k0, s1 = loK ? k4 : k1, s2_ = loK ? k5 : k2;
            r0 = (loK ? k0 : k3) + __shfl_xor_sync(0xffffffffu, s0, 8);
            r1 = (loK ? k1 : k4) + __shfl_xor_sync(0xffffffffu, s1, 8);
            r2 = (loK ? k2 : k5) + __shfl_xor_sync(0xffffffffu, s2_, 8);
        }
        #pragma unroll
        for (int o = 4; o; o >>= 1) {
            r0 += __shfl_xor_sync(0xffffffffu, r0, o);
            r1 += __shfl_xor_sync(0xffffffffu, r1, o);
            r2 += __shfl_xor_sync(0xffffffffu, r2, o);
        }

        float res = r0;
        res = (lk == 1) ? r1 : res;
        res = (lk == 2) ? r2 : res;
        if (lk < 3)
            out[((size_t)b * C_ + (c + rowOff)) * K_ + myk] = res * invSel;
    }
}

extern "C" void kernel_launch(void* const* d_in, const int* in_sizes, int n_in,
                              void* d_out, int out_size) {
    const float* x  = (const float*)d_in[0];   // [256, 2048, 24, 12]
    const float* cl = (const float*)d_in[1];   // [6, 2048]
    float* out = (float*)d_out;                // [B, C, K]

    assign_part_kernel<<<B_ * 2, N_>>>(x, cl);
    argmin_kernel<<<B_, N_>>>(cl);
    sum_kernel<<<B_ * 16, 128>>>(x, out);
}